// round 15
// baseline (speedup 1.0000x reference)
#include <cuda_runtime.h>
#include <math.h>

#define BATCH 2048
#define NZ 128
#define NGEN 8
#define TS 16
#define NTILES 136   // ceil((2048 + 8*15)/16)

typedef unsigned long long u64;

// packed f32x2 helpers (Blackwell FFMA2 path)
__device__ __forceinline__ u64 pk(float lo, float hi) {
    u64 r; asm("mov.b64 %0,{%1,%2};" : "=l"(r) : "f"(lo), "f"(hi)); return r;
}
__device__ __forceinline__ void upk(u64 v, float& lo, float& hi) {
    asm("mov.b64 {%0,%1},%2;" : "=f"(lo), "=f"(hi) : "l"(v));
}
__device__ __forceinline__ void fma2(u64& d, u64 a, u64 b) {
    asm("fma.rn.f32x2 %0,%1,%2,%3;" : "=l"(d) : "l"(a), "l"(b), "l"(d));
}

// ---------------- device scratch (no allocations allowed) ----------------
__device__ float d_h1[BATCH * 256];     // FC1 output
__device__ float d_h2[BATCH * 1568];    // FC2 output (conv input)
__device__ int   d_perm[NTILES * TS];   // samples grouped by generator, -1 padded
__device__ int   d_tileg[NTILES];       // generator per tile, -1 = empty

__device__ __forceinline__ float lrelu(float x) { return x > 0.f ? x : 0.2f * x; }

// ---------------- K0: group samples (match_any-aggregated atomics) --------
__global__ void group_kernel(const int* __restrict__ g_idx) {
    __shared__ int cnt[NGEN], base[NGEN];
    int tid = threadIdx.x;
    int lane = tid & 31;
    if (tid < NGEN) cnt[tid] = 0;
    for (int i = tid; i < NTILES * TS; i += 256)
        d_perm[i] = -1;
    __syncthreads();
    int pos[8], gs[8];
#pragma unroll
    for (int r = 0; r < 8; r++) {
        int b = r * 256 + tid;
        int g = g_idx[b];
        unsigned m = __match_any_sync(0xffffffffu, g);
        int leader = __ffs(m) - 1;
        int rank = __popc(m & ((1u << lane) - 1));
        int basev = 0;
        if (lane == leader) basev = atomicAdd(&cnt[g], __popc(m));
        basev = __shfl_sync(0xffffffffu, basev, leader);
        pos[r] = basev + rank;
        gs[r] = g;
    }
    __syncthreads();
    if (tid == 0) {
        int off = 0;
        for (int g = 0; g < NGEN; g++) {
            base[g] = off;
            off += ((cnt[g] + TS - 1) / TS) * TS;
        }
    }
    __syncthreads();
#pragma unroll
    for (int r = 0; r < 8; r++)
        d_perm[base[gs[r]] + pos[r]] = r * 256 + tid;
    for (int t = tid; t < NTILES; t += 256) {
        int start = t * TS, gg = -1;
        for (int g = 0; g < NGEN; g++) {
            int padded = ((cnt[g] + TS - 1) / TS) * TS;
            if (start >= base[g] && start < base[g] + padded) gg = g;
        }
        d_tileg[t] = gg;
    }
}

// ---------------- K1: FC1  h1 = lrelu(z @ W1[g] + b1[g]) ------------------
// 256 thr: s = tid&7 (samples s, s+8), c = tid>>3 (0..31, 8 outputs each).
__global__ void __launch_bounds__(256) fc1_kernel(
    const float* __restrict__ z, const float* __restrict__ W1,
    const float* __restrict__ b1)
{
    int t = blockIdx.x;
    int g = d_tileg[t];
    if (g < 0) return;
    __shared__ int sids[TS];
    __shared__ __align__(16) float zsm[TS * 132];
    __shared__ __align__(16) float wst[16 * 256];
    int tid = threadIdx.x;
    if (tid < TS) sids[tid] = d_perm[t * TS + tid];
    __syncthreads();
    // z staging, float4
    for (int i4 = tid; i4 < TS * 32; i4 += 256) {
        int s = i4 >> 5, k4 = i4 & 31;
        int b = sids[s];
        float4 vv = (b >= 0) ? ((const float4*)z)[b * 32 + k4]
                             : make_float4(0.f, 0.f, 0.f, 0.f);
        ((float4*)zsm)[s * 33 + k4] = vv;
    }
    int s = tid & 7, c = tid >> 3;
    u64 A0[4], A1[4];
#pragma unroll
    for (int j = 0; j < 4; j++) { A0[j] = 0ULL; A1[j] = 0ULL; }
    const float* Wg = W1 + (size_t)g * NZ * 256;
    for (int kc = 0; kc < 8; kc++) {
        __syncthreads();
#pragma unroll
        for (int j = 0; j < 4; j++) {
            int i4 = tid + 256 * j;          // 1024 float4 per stage
            ((float4*)wst)[i4] = ((const float4*)Wg)[kc * 1024 + i4];
        }
        __syncthreads();
#pragma unroll
        for (int k = 0; k < 16; k++) {
            float hv0 = zsm[s * 132 + kc * 16 + k];
            float hv1 = zsm[(s + 8) * 132 + kc * 16 + k];
            u64 H0 = pk(hv0, hv0), H1 = pk(hv1, hv1);
            const ulonglong2* wp = (const ulonglong2*)&wst[k * 256 + c * 8];
#pragma unroll
            for (int j = 0; j < 2; j++) {
                ulonglong2 ww = wp[j];
                fma2(A0[2 * j],     ww.x, H0);
                fma2(A1[2 * j],     ww.x, H1);
                fma2(A0[2 * j + 1], ww.y, H0);
                fma2(A1[2 * j + 1], ww.y, H1);
            }
        }
    }
    const float* bp = b1 + g * 256 + c * 8;
    int b0 = sids[s], b1v = sids[s + 8];
    if (b0 >= 0) {
        float2* dst = (float2*)&d_h1[b0 * 256 + c * 8];
#pragma unroll
        for (int j = 0; j < 4; j++) {
            float lo, hi; upk(A0[j], lo, hi);
            float2 vv;
            vv.x = lrelu(lo + bp[2 * j]);
            vv.y = lrelu(hi + bp[2 * j + 1]);
            dst[j] = vv;
        }
    }
    if (b1v >= 0) {
        float2* dst = (float2*)&d_h1[b1v * 256 + c * 8];
#pragma unroll
        for (int j = 0; j < 4; j++) {
            float lo, hi; upk(A1[j], lo, hi);
            float2 vv;
            vv.x = lrelu(lo + bp[2 * j]);
            vv.y = lrelu(hi + bp[2 * j + 1]);
            dst[j] = vv;
        }
    }
}

// ---------------- K2: FC2  h2 = lrelu(h1 @ W2[g] + b2[g]) -----------------
// 224 thr, q in 0..1 (784 outputs per CTA): s = tid&7 (samples s, s+8),
// c = tid>>3 (0..27, 28 outputs each). Weight loads are LDS.128 (c*28
// floats = 112B, 16B-aligned). Dynamic smem:
//   h1sm [0,4160) 16x260 | wst [4160,16704) 16x784
#define FC2_SMEMF 16704

__global__ void __launch_bounds__(224) fc2_kernel(
    const float* __restrict__ W2, const float* __restrict__ b2)
{
    extern __shared__ float dsm[];
    float* h1sm = dsm;
    float* wst  = dsm + 4160;
    __shared__ int sids[TS];
    int t = blockIdx.x, q = blockIdx.y;   // q in 0..1
    int g = d_tileg[t];
    if (g < 0) return;
    int tid = threadIdx.x;
    if (tid < TS) sids[tid] = d_perm[t * TS + tid];
    __syncthreads();
    // h1 staging, float4 (1024 float4)
    for (int i4 = tid; i4 < TS * 64; i4 += 224) {
        int s = i4 >> 6, k4 = i4 & 63;
        int b = sids[s];
        float4 vv = (b >= 0) ? ((const float4*)d_h1)[b * 64 + k4]
                             : make_float4(0.f, 0.f, 0.f, 0.f);
        ((float4*)h1sm)[s * 65 + k4] = vv;
    }
    int s = tid & 7, c = tid >> 3;
    u64 A0[14], A1[14];
#pragma unroll
    for (int j = 0; j < 14; j++) { A0[j] = 0ULL; A1[j] = 0ULL; }
    const float* Wg = W2 + (size_t)g * 256 * 1568 + q * 784;
    for (int kc = 0; kc < 16; kc++) {
        __syncthreads();
#pragma unroll
        for (int j = 0; j < 14; j++) {       // 3136 float4 per stage
            int i4 = tid + 224 * j;
            int row = i4 / 196, c4 = i4 - row * 196;
            ((float4*)wst)[i4] =
                ((const float4*)Wg)[(kc * 16 + row) * 392 + c4];
        }
        __syncthreads();
#pragma unroll
        for (int k = 0; k < 16; k++) {
            float hv0 = h1sm[s * 260 + kc * 16 + k];
            float hv1 = h1sm[(s + 8) * 260 + kc * 16 + k];
            u64 H0 = pk(hv0, hv0), H1 = pk(hv1, hv1);
            const ulonglong2* wp = (const ulonglong2*)&wst[k * 784 + c * 28];
#pragma unroll
            for (int j = 0; j < 7; j++) {
                ulonglong2 ww = wp[j];
                fma2(A0[2 * j],     ww.x, H0);
                fma2(A1[2 * j],     ww.x, H1);
                fma2(A0[2 * j + 1], ww.y, H0);
                fma2(A1[2 * j + 1], ww.y, H1);
            }
        }
    }
    int ob = q * 784 + c * 28;
    const float* bp = b2 + g * 1568 + ob;
    int b0 = sids[s], b1v = sids[s + 8];
    if (b0 >= 0) {
        float2* dst = (float2*)&d_h2[(size_t)b0 * 1568 + ob];
#pragma unroll
        for (int j = 0; j < 14; j++) {
            float lo, hi; upk(A0[j], lo, hi);
            float2 vv;
            vv.x = lrelu(lo + bp[2 * j]);
            vv.y = lrelu(hi + bp[2 * j + 1]);
            dst[j] = vv;
        }
    }
    if (b1v >= 0) {
        float2* dst = (float2*)&d_h2[(size_t)b1v * 1568 + ob];
#pragma unroll
        for (int j = 0; j < 14; j++) {
            float lo, hi; upk(A1[j], lo, hi);
            float2 vv;
            vv.x = lrelu(lo + bp[2 * j]);
            vv.y = lrelu(hi + bp[2 * j + 1]);
            dst[j] = vv;
        }
    }
}

// ---------------- K3: conv chain, 2 samples per CTA (512 threads) ---------
// Weight buffer layout pairs the two taps of each parity class contiguously:
//   slot(ci,jy,par) = (ci*4+jy)*2 + par,  par = jx & 1
//   convT1: wb[slot*32 + (co&~1)*2 + (jx>>1)*2 + (co&1)]   (co in 0..15)
//   convT2: wb[slot*16 + (co&~1)*2 + (jx>>1)*2 + (co&1)]   (co in 0..7)
// -> compute loads one LDS.128 = (w_lo(co), w_lo(co+1), w_hi(co), w_hi(co+1)).
#define SM_HALF 11776
#define SM_WB 23552
#define SM_TOTALF 27776

__device__ __forceinline__ int x2idx(int ch, int r, int c) {
    int sw = (r >> 1) & 3;
    return ch * 256 + r * 16 + ((((c >> 2) ^ sw)) << 2) + (c & 3);
}
__device__ __forceinline__ int x3idx(int ch, int r, int c) {
    int sw = r & 7;
    return ch * 960 + r * 32 + (((c >> 2) ^ sw) << 2) + (c & 3);
}

template<int PX>
__device__ __forceinline__ void convt1_half(
    const float* __restrict__ x1q, const float* __restrict__ wb,
    int my, int py, int co, u64* A)
{
#pragma unroll
    for (int ci = 0; ci < 16; ci++) {
        const float* xc = x1q + ci * 108;           // 9*12, no swizzle
#pragma unroll
        for (int d = 0; d < 2; d++) {
            int row = my + py + 1 - d;
            float r[12];
            const float4* rp = (const float4*)(xc + row * 12);
#pragma unroll
            for (int tt = 0; tt < 3; tt++) {
                float4 vv = rp[tt];
                r[4 * tt] = vv.x; r[4 * tt + 1] = vv.y;
                r[4 * tt + 2] = vv.z; r[4 * tt + 3] = vv.w;
            }
            int jy = 1 - py + 2 * d;
            // paired taps jx = (1-PX) and (3-PX), one LDS.128
            ulonglong2 wq = *(const ulonglong2*)
                &wb[(((ci * 4 + jy) * 2 + (1 - PX)) << 5) + co * 2];
            u64 w0 = wq.x, w1 = wq.y;
            u64 xa = pk(r[PX], r[PX]);
#pragma unroll
            for (int m = 0; m < 7; m++) {
                u64 xb = pk(r[PX + 1 + m], r[PX + 1 + m]);
                fma2(A[m], w1, xa);
                fma2(A[m], w0, xb);
                xa = xb;
            }
        }
    }
}

template<int PX>
__device__ __forceinline__ void convt2_compute(
    const float* __restrict__ x2, const float* __restrict__ wb,
    int my, int py, int co, u64* A)
{
#pragma unroll 4
    for (int ci = 0; ci < 16; ci++) {
        const float* xc = x2 + ci * 256;            // 16x16 swizzled
#pragma unroll
        for (int d = 0; d < 2; d++) {
            int row = my + py + 1 - d;
            int sw = (row >> 1) & 3;
            const float* rp = xc + row * 16;
            float r[16];
#pragma unroll
            for (int tt = 0; tt < 4; tt++) {
                float4 vv = *(const float4*)(rp + ((tt ^ sw) << 2));
                r[4 * tt] = vv.x; r[4 * tt + 1] = vv.y;
                r[4 * tt + 2] = vv.z; r[4 * tt + 3] = vv.w;
            }
            int jy = 1 - py + 2 * d;
            ulonglong2 wq = *(const ulonglong2*)
                &wb[(((ci * 4 + jy) * 2 + (1 - PX)) << 4) + co * 2];
            u64 w0 = wq.x, w1 = wq.y;
            u64 xa = pk(r[PX], r[PX]);
#pragma unroll
            for (int m = 0; m < 14; m++) {
                u64 xb = pk(r[PX + 1 + m], r[PX + 1 + m]);
                fma2(A[m], w1, xa);
                fma2(A[m], w0, xb);
                xa = xb;
            }
        }
    }
}

__global__ void __launch_bounds__(512, 2) conv_kernel(
    const float* __restrict__ cw1, const float* __restrict__ cb1,
    const float* __restrict__ cw2, const float* __restrict__ cb2,
    const float* __restrict__ cw3, const float* __restrict__ cb3,
    float* __restrict__ out)
{
    extern __shared__ float sm[];
    int tid = threadIdx.x;
    int half = tid >> 8, stid = tid & 255;
    int tile = blockIdx.x >> 3;          // 8 CTAs cover one 16-slot tile
    int g = d_tileg[tile];
    if (g < 0) return;
    int b = d_perm[blockIdx.x * 2 + half];   // may be -1 (padded slot)
    // b is warp-uniform (half = tid>>8): dead slots skip whole warps' compute.

    float* x2 = sm + half * SM_HALF;
    float* x3 = x2 + 4096;
    float* x1 = x3;                      // aliases x3 (dead before x3 written)
    float* wb = sm + SM_WB;

    int cls = stid >> 6;                 // warp-uniform parity class
    int py = cls >> 1, px = cls & 1;
    int v = stid & 63;

    // ---- halo-only zeroing of x1 and x2 (per half) ----
    if (b >= 0) {
        for (int i = stid; i < 32 * 38; i += 256) {  // x1: 38 halo elems/ci
            int ci = i / 38, k = i - ci * 38;
            int row, col;
            if (k < 12)      { row = 0; col = k; }
            else if (k < 24) { row = 8; col = k - 12; }
            else { int k2 = k - 24; row = 1 + (k2 >> 1); col = (k2 & 1) * 8; }
            x1[ci * 108 + row * 12 + col] = 0.f;
        }
        for (int i = stid; i < 16 * 60; i += 256) {  // x2: 60 halo elems/ci
            int ci = i / 60, k = i - ci * 60;
            int row, col;
            if (k < 16)      { row = 0;  col = k; }
            else if (k < 32) { row = 15; col = k - 16; }
            else { int k2 = k - 32; row = 1 + (k2 >> 1); col = (k2 & 1) * 15; }
            x2[x2idx(ci, row, col)] = 0.f;
        }
        // load conv input [32,7,7] into padded x1 interior (stride 12), float4
        const float4* src = (const float4*)(d_h2 + (size_t)b * 1568);
        for (int i4 = stid; i4 < 392; i4 += 256) {
            float4 w = src[i4];
            int base = i4 * 4;
#pragma unroll
            for (int e = 0; e < 4; e++) {
                int idx = base + e;
                int ci = idx / 49, rem = idx - ci * 49;
                int rr = rem / 7, cc = rem - rr * 7;
                float val = (e == 0) ? w.x : (e == 1) ? w.y : (e == 2) ? w.z : w.w;
                x1[ci * 108 + (rr + 1) * 12 + cc + 1] = val;
            }
        }
    }

    // ---- convT1: [32,7,7] -> [16,14,14], cw1 staged in 2 halves ----
    int my1 = v >> 3, co1 = (v & 7) * 2;             // valid when v < 56
    u64 A1c[7];
#pragma unroll
    for (int m = 0; m < 7; m++) A1c[m] = 0ULL;

    for (int hc = 0; hc < 2; hc++) {
        __syncthreads();
        for (int i4 = tid; i4 < 1024; i4 += 512) {   // 4096 floats, float4 LDG
            float4 w = ((const float4*)(cw1 + (size_t)g * 8192 + hc * 4096))[i4];
            int base = i4 * 4;
            int ci = base >> 8, cc = (base >> 4) & 15, jy = (base >> 2) & 3;
            int slot0 = (ci * 4 + jy) * 2;           // parity 0 (jx 0,2)
            int grp = (cc & ~1) * 2 + (cc & 1);
            float* d0 = &wb[(slot0 << 5) + grp];         // jx=0 -> lo, jx=2 -> hi
            d0[0] = w.x; d0[2] = w.z;
            float* d1 = &wb[((slot0 + 1) << 5) + grp];   // jx=1 -> lo, jx=3 -> hi
            d1[0] = w.y; d1[2] = w.w;
        }
        __syncthreads();
        if (v < 56 && b >= 0) {
            const float* x1q = x1 + hc * 16 * 108;
            if (px == 0) convt1_half<0>(x1q, wb, my1, py, co1, A1c);
            else         convt1_half<1>(x1q, wb, my1, py, co1, A1c);
        }
    }
    if (v < 56 && b >= 0) {
        float bb0 = cb1[g * 16 + co1], bb1 = cb1[g * 16 + co1 + 1];
        int oy = 2 * my1 + py;
#pragma unroll
        for (int m = 0; m < 7; m++) {
            int ox = 2 * m + px;
            float lo, hi; upk(A1c[m], lo, hi);
            x2[x2idx(co1,     oy + 1, ox + 1)] = lrelu(lo + bb0);
            x2[x2idx(co1 + 1, oy + 1, ox + 1)] = lrelu(hi + bb1);
        }
    }
    __syncthreads();     // convT1 done; x1 dead

    // halo-zero x3 (per half), stage cw2 + cw3 (all 512 threads)
    if (b >= 0) {
        for (int i = stid; i < 8 * 116; i += 256) {
            int ci = i / 116, k = i - ci * 116;
            int row, col;
            if (k < 30)      { row = 0;  col = k; }
            else if (k < 60) { row = 29; col = k - 30; }
            else { int k2 = k - 60; row = 1 + (k2 >> 1); col = (k2 & 1) * 29; }
            x3[x3idx(ci, row, col)] = 0.f;
        }
    }
    {
        int i4 = tid;                                 // 2048 floats, 1 f4/thread
        float4 w = ((const float4*)(cw2 + (size_t)g * 2048))[i4];
        int base = i4 * 4;
        int ci = base >> 7, cc = (base >> 4) & 7, jy = (base >> 2) & 3;
        int slot0 = (ci * 4 + jy) * 2;
        int grp = (cc & ~1) * 2 + (cc & 1);
        float* d0 = &wb[(slot0 << 4) + grp];
        d0[0] = w.x; d0[2] = w.z;
        float* d1 = &wb[((slot0 + 1) << 4) + grp];
        d1[0] = w.y; d1[2] = w.w;
    }
    if (tid < 72) wb[2048 + tid] = cw3[g * 72 + tid];
    __syncthreads();

    // ---- convT2: [16,14,14] -> [8,28,28] ----
    if (v < 56 && b >= 0) {
        int my = v >> 2, co = (v & 3) * 2;
        u64 A2c[14];
#pragma unroll
        for (int m = 0; m < 14; m++) A2c[m] = 0ULL;
        if (px == 0) convt2_compute<0>(x2, wb, my, py, co, A2c);
        else         convt2_compute<1>(x2, wb, my, py, co, A2c);
        float bb0 = cb2[g * 8 + co], bb1 = cb2[g * 8 + co + 1];
        int oy = 2 * my + py;
#pragma unroll
        for (int m = 0; m < 14; m++) {
            int ox = 2 * m + px;
            float lo, hi; upk(A2c[m], lo, hi);
            x3[x3idx(co,     oy + 1, ox + 1)] = lrelu(lo + bb0);
            x3[x3idx(co + 1, oy + 1, ox + 1)] = lrelu(hi + bb1);
        }
    }
    __syncthreads();

    // ---- convT3 (stride1 k3 p1): [8,28,28] -> [1,28,28], tanh ----
    if (stid < 196 && b >= 0) {
        int oy = stid / 7, s = stid - oy * 7;        // s in 0..6
        float bb = cb3[g];
        float acc[4];
#pragma unroll
        for (int u = 0; u < 4; u++) acc[u] = bb;
        const float* w3 = wb + 2048;
        for (int ci = 0; ci < 8; ci++) {
#pragma unroll
            for (int jy = 0; jy < 3; jy++) {
                int row = oy + 2 - jy;
                int sw = row & 7;
                const float* base = x3 + (ci * 30 + row) * 32;
                float r[8];
                float4 v0 = *(const float4*)(base + ((s ^ sw) << 2));
                float4 v1 = *(const float4*)(base + (((s + 1) ^ sw) << 2));
                r[0] = v0.x; r[1] = v0.y; r[2] = v0.z; r[3] = v0.w;
                r[4] = v1.x; r[5] = v1.y; r[6] = v1.z; r[7] = v1.w;
                const float* wr = w3 + ci * 9 + jy * 3;
#pragma unroll
                for (int jx = 0; jx < 3; jx++) {
                    float wv = wr[jx];
#pragma unroll
                    for (int u = 0; u < 4; u++)
                        acc[u] += wv * r[u + 2 - jx];
                }
            }
        }
        float4 o;
        o.x = tanhf(acc[0]); o.y = tanhf(acc[1]);
        o.z = tanhf(acc[2]); o.w = tanhf(acc[3]);
        *(float4*)(out + (size_t)b * 784 + oy * 28 + s * 4) = o;
    }
}

// ---------------- launch ----------------
extern "C" void kernel_launch(void* const* d_in, const int* in_sizes, int n_in,
                              void* d_out, int out_size)
{
    (void)in_sizes; (void)n_in; (void)out_size;
    const float* z   = (const float*)d_in[0];
    const int*   gi  = (const int*)d_in[1];
    const float* W1  = (const float*)d_in[2];
    const float* b1  = (const float*)d_in[3];
    const float* W2  = (const float*)d_in[4];
    const float* b2  = (const float*)d_in[5];
    const float* cw1 = (const float*)d_in[6];
    const float* cb1 = (const float*)d_in[7];
    const float* cw2 = (const float*)d_in[8];
    const float* cb2 = (const float*)d_in[9];
    const float* cw3 = (const float*)d_in[10];
    const float* cb3 = (const float*)d_in[11];
    float* out = (float*)d_out;

    group_kernel<<<1, 256>>>(gi);
    fc1_kernel<<<NTILES, 256>>>(z, W1, b1);
    cudaFuncSetAttribute(fc2_kernel,
                         cudaFuncAttributeMaxDynamicSharedMemorySize,
                         FC2_SMEMF * 4);
    fc2_kernel<<<dim3(NTILES, 2), 224, FC2_SMEMF * 4>>>(W2, b2);
    cudaFuncSetAttribute(conv_kernel,
                         cudaFuncAttributeMaxDynamicSharedMemorySize,
                         SM_TOTALF * 4);
    conv_kernel<<<NTILES * 8, 512, SM_TOTALF * 4>>>(cw1, cb1, cw2, cb2,
                                                    cw3, cb3, out);
}

// round 16
// speedup vs baseline: 1.8467x; 1.8467x over previous
#include <cuda_runtime.h>
#include <math.h>

#define BATCH 2048
#define NZ 128
#define NGEN 8
#define TS 16
#define NTILES 136   // ceil((2048 + 8*15)/16)

typedef unsigned long long u64;

// packed f32x2 helpers (Blackwell FFMA2 path)
__device__ __forceinline__ u64 pk(float lo, float hi) {
    u64 r; asm("mov.b64 %0,{%1,%2};" : "=l"(r) : "f"(lo), "f"(hi)); return r;
}
__device__ __forceinline__ void upk(u64 v, float& lo, float& hi) {
    asm("mov.b64 {%0,%1},%2;" : "=f"(lo), "=f"(hi) : "l"(v));
}
__device__ __forceinline__ void fma2(u64& d, u64 a, u64 b) {
    asm("fma.rn.f32x2 %0,%1,%2,%3;" : "=l"(d) : "l"(a), "l"(b), "l"(d));
}

// ---------------- device scratch (no allocations allowed) ----------------
__device__ float d_h1[BATCH * 256];     // FC1 output
__device__ float d_h2[BATCH * 1568];    // FC2 output (conv input)
__device__ int   d_perm[NTILES * TS];   // samples grouped by generator, -1 padded
__device__ int   d_tileg[NTILES];       // generator per tile, -1 = empty

__device__ __forceinline__ float lrelu(float x) { return x > 0.f ? x : 0.2f * x; }

// ---------------- K0: group samples (match_any-aggregated atomics) --------
__global__ void group_kernel(const int* __restrict__ g_idx) {
    __shared__ int cnt[NGEN], base[NGEN];
    int tid = threadIdx.x;
    int lane = tid & 31;
    if (tid < NGEN) cnt[tid] = 0;
    for (int i = tid; i < NTILES * TS; i += 256)
        d_perm[i] = -1;
    __syncthreads();
    int pos[8], gs[8];
#pragma unroll
    for (int r = 0; r < 8; r++) {
        int b = r * 256 + tid;
        int g = g_idx[b];
        unsigned m = __match_any_sync(0xffffffffu, g);
        int leader = __ffs(m) - 1;
        int rank = __popc(m & ((1u << lane) - 1));
        int basev = 0;
        if (lane == leader) basev = atomicAdd(&cnt[g], __popc(m));
        basev = __shfl_sync(0xffffffffu, basev, leader);
        pos[r] = basev + rank;
        gs[r] = g;
    }
    __syncthreads();
    if (tid == 0) {
        int off = 0;
        for (int g = 0; g < NGEN; g++) {
            base[g] = off;
            off += ((cnt[g] + TS - 1) / TS) * TS;
        }
    }
    __syncthreads();
#pragma unroll
    for (int r = 0; r < 8; r++)
        d_perm[base[gs[r]] + pos[r]] = r * 256 + tid;
    for (int t = tid; t < NTILES; t += 256) {
        int start = t * TS, gg = -1;
        for (int g = 0; g < NGEN; g++) {
            int padded = ((cnt[g] + TS - 1) / TS) * TS;
            if (start >= base[g] && start < base[g] + padded) gg = g;
        }
        d_tileg[t] = gg;
    }
}

// ---------------- K1: FC1  h1 = lrelu(z @ W1[g] + b1[g]) ------------------
// 256 thr: s = tid&7 (samples s, s+8), c = tid>>3 (0..31, 8 outputs each).
__global__ void __launch_bounds__(256) fc1_kernel(
    const float* __restrict__ z, const float* __restrict__ W1,
    const float* __restrict__ b1)
{
    int t = blockIdx.x;
    int g = d_tileg[t];
    if (g < 0) return;
    __shared__ int sids[TS];
    __shared__ __align__(16) float zsm[TS * 132];
    __shared__ __align__(16) float wst[16 * 256];
    int tid = threadIdx.x;
    if (tid < TS) sids[tid] = d_perm[t * TS + tid];
    __syncthreads();
    // z staging, float4
    for (int i4 = tid; i4 < TS * 32; i4 += 256) {
        int s = i4 >> 5, k4 = i4 & 31;
        int b = sids[s];
        float4 vv = (b >= 0) ? ((const float4*)z)[b * 32 + k4]
                             : make_float4(0.f, 0.f, 0.f, 0.f);
        ((float4*)zsm)[s * 33 + k4] = vv;
    }
    int s = tid & 7, c = tid >> 3;
    u64 A0[4], A1[4];
#pragma unroll
    for (int j = 0; j < 4; j++) { A0[j] = 0ULL; A1[j] = 0ULL; }
    const float* Wg = W1 + (size_t)g * NZ * 256;
    for (int kc = 0; kc < 8; kc++) {
        __syncthreads();
#pragma unroll
        for (int j = 0; j < 4; j++) {
            int i4 = tid + 256 * j;          // 1024 float4 per stage
            ((float4*)wst)[i4] = ((const float4*)Wg)[kc * 1024 + i4];
        }
        __syncthreads();
#pragma unroll
        for (int k = 0; k < 16; k++) {
            float hv0 = zsm[s * 132 + kc * 16 + k];
            float hv1 = zsm[(s + 8) * 132 + kc * 16 + k];
            u64 H0 = pk(hv0, hv0), H1 = pk(hv1, hv1);
            const u64* wp = (const u64*)&wst[k * 256 + c * 8];
#pragma unroll
            for (int j = 0; j < 4; j++) {
                u64 w = wp[j];
                fma2(A0[j], w, H0);
                fma2(A1[j], w, H1);
            }
        }
    }
    const float* bp = b1 + g * 256 + c * 8;
    int b0 = sids[s], b1v = sids[s + 8];
    if (b0 >= 0) {
        float2* dst = (float2*)&d_h1[b0 * 256 + c * 8];
#pragma unroll
        for (int j = 0; j < 4; j++) {
            float lo, hi; upk(A0[j], lo, hi);
            float2 vv;
            vv.x = lrelu(lo + bp[2 * j]);
            vv.y = lrelu(hi + bp[2 * j + 1]);
            dst[j] = vv;
        }
    }
    if (b1v >= 0) {
        float2* dst = (float2*)&d_h1[b1v * 256 + c * 8];
#pragma unroll
        for (int j = 0; j < 4; j++) {
            float lo, hi; upk(A1[j], lo, hi);
            float2 vv;
            vv.x = lrelu(lo + bp[2 * j]);
            vv.y = lrelu(hi + bp[2 * j + 1]);
            dst[j] = vv;
        }
    }
}

// ---------------- K2: FC2  h2 = lrelu(h1 @ W2[g] + b2[g]) -----------------
// 224 thr, q in 0..1 (784 outputs per CTA): s = tid&7 (samples s, s+8),
// c = tid>>3 (0..27, 28 outputs each). Halved N-split doubles weight reuse
// per staged tile -> staging L2 traffic halves vs 4-way split.
// Dynamic smem: h1sm [0,4160) 16x260 | wst [4160,16704) 16x784
#define FC2_SMEMF 16704

__global__ void __launch_bounds__(224) fc2_kernel(
    const float* __restrict__ W2, const float* __restrict__ b2)
{
    extern __shared__ float dsm[];
    float* h1sm = dsm;
    float* wst  = dsm + 4160;
    __shared__ int sids[TS];
    int t = blockIdx.x, q = blockIdx.y;   // q in 0..1
    int g = d_tileg[t];
    if (g < 0) return;
    int tid = threadIdx.x;
    if (tid < TS) sids[tid] = d_perm[t * TS + tid];
    __syncthreads();
    // h1 staging, float4 (1024 float4)
    for (int i4 = tid; i4 < TS * 64; i4 += 224) {
        int s = i4 >> 6, k4 = i4 & 63;
        int b = sids[s];
        float4 vv = (b >= 0) ? ((const float4*)d_h1)[b * 64 + k4]
                             : make_float4(0.f, 0.f, 0.f, 0.f);
        ((float4*)h1sm)[s * 65 + k4] = vv;
    }
    int s = tid & 7, c = tid >> 3;
    u64 A0[14], A1[14];
#pragma unroll
    for (int j = 0; j < 14; j++) { A0[j] = 0ULL; A1[j] = 0ULL; }
    const float* Wg = W2 + (size_t)g * 256 * 1568 + q * 784;
    for (int kc = 0; kc < 16; kc++) {
        __syncthreads();
#pragma unroll
        for (int j = 0; j < 14; j++) {       // 3136 float4 per stage
            int i4 = tid + 224 * j;
            int row = i4 / 196, c4 = i4 - row * 196;
            ((float4*)wst)[i4] =
                ((const float4*)Wg)[(kc * 16 + row) * 392 + c4];
        }
        __syncthreads();
#pragma unroll
        for (int k = 0; k < 16; k++) {
            float hv0 = h1sm[s * 260 + kc * 16 + k];
            float hv1 = h1sm[(s + 8) * 260 + kc * 16 + k];
            u64 H0 = pk(hv0, hv0), H1 = pk(hv1, hv1);
            const u64* wp = (const u64*)&wst[k * 784 + c * 28];
#pragma unroll
            for (int j = 0; j < 14; j++) {
                u64 w = wp[j];
                fma2(A0[j], w, H0);
                fma2(A1[j], w, H1);
            }
        }
    }
    int ob = q * 784 + c * 28;
    const float* bp = b2 + g * 1568 + ob;
    int b0 = sids[s], b1v = sids[s + 8];
    if (b0 >= 0) {
        float2* dst = (float2*)&d_h2[(size_t)b0 * 1568 + ob];
#pragma unroll
        for (int j = 0; j < 14; j++) {
            float lo, hi; upk(A0[j], lo, hi);
            float2 vv;
            vv.x = lrelu(lo + bp[2 * j]);
            vv.y = lrelu(hi + bp[2 * j + 1]);
            dst[j] = vv;
        }
    }
    if (b1v >= 0) {
        float2* dst = (float2*)&d_h2[(size_t)b1v * 1568 + ob];
#pragma unroll
        for (int j = 0; j < 14; j++) {
            float lo, hi; upk(A1[j], lo, hi);
            float2 vv;
            vv.x = lrelu(lo + bp[2 * j]);
            vv.y = lrelu(hi + bp[2 * j + 1]);
            dst[j] = vv;
        }
    }
}

// ---------------- K3: conv chain, 2 samples per CTA (512 threads) ---------
#define SM_HALF 11776
#define SM_WB 23552
#define SM_TOTALF 27776

__device__ __forceinline__ int x2idx(int ch, int r, int c) {
    int sw = (r >> 1) & 3;
    return ch * 256 + r * 16 + ((((c >> 2) ^ sw)) << 2) + (c & 3);
}
__device__ __forceinline__ int x3idx(int ch, int r, int c) {
    int sw = r & 7;
    return ch * 960 + r * 32 + (((c >> 2) ^ sw) << 2) + (c & 3);
}

template<int PX>
__device__ __forceinline__ void convt1_half(
    const float* __restrict__ x1q, const float* __restrict__ wb,
    int my, int py, int co, u64* A)
{
#pragma unroll
    for (int ci = 0; ci < 16; ci++) {
        const float* xc = x1q + ci * 108;           // 9*12, no swizzle
#pragma unroll
        for (int d = 0; d < 2; d++) {
            int row = my + py + 1 - d;
            float r[12];
            const float4* rp = (const float4*)(xc + row * 12);
#pragma unroll
            for (int tt = 0; tt < 3; tt++) {
                float4 vv = rp[tt];
                r[4 * tt] = vv.x; r[4 * tt + 1] = vv.y;
                r[4 * tt + 2] = vv.z; r[4 * tt + 3] = vv.w;
            }
            int jy = 1 - py + 2 * d;
            u64 w0 = *(const u64*)&wb[((ci * 4 + jy) * 4 + (1 - PX)) * 16 + co];
            u64 w1 = *(const u64*)&wb[((ci * 4 + jy) * 4 + (3 - PX)) * 16 + co];
            u64 xa = pk(r[PX], r[PX]);
#pragma unroll
            for (int m = 0; m < 7; m++) {
                u64 xb = pk(r[PX + 1 + m], r[PX + 1 + m]);
                fma2(A[m], w1, xa);
                fma2(A[m], w0, xb);
                xa = xb;
            }
        }
    }
}

template<int PX>
__device__ __forceinline__ void convt2_compute(
    const float* __restrict__ x2, const float* __restrict__ wb,
    int my, int py, int co, u64* A)
{
#pragma unroll 4
    for (int ci = 0; ci < 16; ci++) {
        const float* xc = x2 + ci * 256;            // 16x16 swizzled
#pragma unroll
        for (int d = 0; d < 2; d++) {
            int row = my + py + 1 - d;
            int sw = (row >> 1) & 3;
            const float* rp = xc + row * 16;
            float r[16];
#pragma unroll
            for (int tt = 0; tt < 4; tt++) {
                float4 vv = *(const float4*)(rp + ((tt ^ sw) << 2));
                r[4 * tt] = vv.x; r[4 * tt + 1] = vv.y;
                r[4 * tt + 2] = vv.z; r[4 * tt + 3] = vv.w;
            }
            int jy = 1 - py + 2 * d;
            u64 w0 = *(const u64*)&wb[((ci * 4 + jy) * 4 + (1 - PX)) * 8 + co];
            u64 w1 = *(const u64*)&wb[((ci * 4 + jy) * 4 + (3 - PX)) * 8 + co];
            u64 xa = pk(r[PX], r[PX]);
#pragma unroll
            for (int m = 0; m < 14; m++) {
                u64 xb = pk(r[PX + 1 + m], r[PX + 1 + m]);
                fma2(A[m], w1, xa);
                fma2(A[m], w0, xb);
                xa = xb;
            }
        }
    }
}

__global__ void __launch_bounds__(512, 2) conv_kernel(
    const float* __restrict__ cw1, const float* __restrict__ cb1,
    const float* __restrict__ cw2, const float* __restrict__ cb2,
    const float* __restrict__ cw3, const float* __restrict__ cb3,
    float* __restrict__ out)
{
    extern __shared__ float sm[];
    int tid = threadIdx.x;
    int half = tid >> 8, stid = tid & 255;
    int tile = blockIdx.x >> 3;          // 8 CTAs cover one 16-slot tile
    int g = d_tileg[tile];
    if (g < 0) return;
    int b = d_perm[blockIdx.x * 2 + half];   // may be -1 (padded slot)
    // b is warp-uniform (half = tid>>8): dead slots skip whole warps' compute.

    float* x2 = sm + half * SM_HALF;
    float* x3 = x2 + 4096;
    float* x1 = x3;                      // aliases x3 (dead before x3 written)
    float* wb = sm + SM_WB;

    int cls = stid >> 6;                 // warp-uniform parity class
    int py = cls >> 1, px = cls & 1;
    int v = stid & 63;

    // ---- halo-only zeroing of x1 and x2 (per half) ----
    if (b >= 0) {
        for (int i = stid; i < 32 * 38; i += 256) {  // x1: 38 halo elems/ci
            int ci = i / 38, k = i - ci * 38;
            int row, col;
            if (k < 12)      { row = 0; col = k; }
            else if (k < 24) { row = 8; col = k - 12; }
            else { int k2 = k - 24; row = 1 + (k2 >> 1); col = (k2 & 1) * 8; }
            x1[ci * 108 + row * 12 + col] = 0.f;
        }
        for (int i = stid; i < 16 * 60; i += 256) {  // x2: 60 halo elems/ci
            int ci = i / 60, k = i - ci * 60;
            int row, col;
            if (k < 16)      { row = 0;  col = k; }
            else if (k < 32) { row = 15; col = k - 16; }
            else { int k2 = k - 32; row = 1 + (k2 >> 1); col = (k2 & 1) * 15; }
            x2[x2idx(ci, row, col)] = 0.f;
        }
        // load conv input [32,7,7] into padded x1 interior (stride 12), float4
        const float4* src = (const float4*)(d_h2 + (size_t)b * 1568);
        for (int i4 = stid; i4 < 392; i4 += 256) {
            float4 w = src[i4];
            int base = i4 * 4;
#pragma unroll
            for (int e = 0; e < 4; e++) {
                int idx = base + e;
                int ci = idx / 49, rem = idx - ci * 49;
                int rr = rem / 7, cc = rem - rr * 7;
                float val = (e == 0) ? w.x : (e == 1) ? w.y : (e == 2) ? w.z : w.w;
                x1[ci * 108 + (rr + 1) * 12 + cc + 1] = val;
            }
        }
    }

    // ---- convT1: [32,7,7] -> [16,14,14], cw1 staged in 2 halves ----
    int my1 = v >> 3, co1 = (v & 7) * 2;             // valid when v < 56
    u64 A1c[7];
#pragma unroll
    for (int m = 0; m < 7; m++) A1c[m] = 0ULL;

    for (int hc = 0; hc < 2; hc++) {
        __syncthreads();
        for (int i4 = tid; i4 < 1024; i4 += 512) {   // 4096 floats, float4 LDG
            float4 w = ((const float4*)(cw1 + (size_t)g * 8192 + hc * 4096))[i4];
            int base = i4 * 4;
            int ci = base >> 8, cc = (base >> 4) & 15, jy = (base >> 2) & 3;
            float* dst = &wb[((ci * 4 + jy) * 4) * 16 + cc];
            dst[0] = w.x; dst[16] = w.y; dst[32] = w.z; dst[48] = w.w;
        }
        __syncthreads();
        if (v < 56 && b >= 0) {
            const float* x1q = x1 + hc * 16 * 108;
            if (px == 0) convt1_half<0>(x1q, wb, my1, py, co1, A1c);
            else         convt1_half<1>(x1q, wb, my1, py, co1, A1c);
        }
    }
    if (v < 56 && b >= 0) {
        float bb0 = cb1[g * 16 + co1], bb1 = cb1[g * 16 + co1 + 1];
        int oy = 2 * my1 + py;
#pragma unroll
        for (int m = 0; m < 7; m++) {
            int ox = 2 * m + px;
            float lo, hi; upk(A1c[m], lo, hi);
            x2[x2idx(co1,     oy + 1, ox + 1)] = lrelu(lo + bb0);
            x2[x2idx(co1 + 1, oy + 1, ox + 1)] = lrelu(hi + bb1);
        }
    }
    __syncthreads();     // convT1 done; x1 dead

    // halo-zero x3 (per half), stage cw2 + cw3 (all 512 threads)
    if (b >= 0) {
        for (int i = stid; i < 8 * 116; i += 256) {
            int ci = i / 116, k = i - ci * 116;
            int row, col;
            if (k < 30)      { row = 0;  col = k; }
            else if (k < 60) { row = 29; col = k - 30; }
            else { int k2 = k - 60; row = 1 + (k2 >> 1); col = (k2 & 1) * 29; }
            x3[x3idx(ci, row, col)] = 0.f;
        }
    }
    {
        int i4 = tid;                                 // 2048 floats, 1 f4/thread
        float4 w = ((const float4*)(cw2 + (size_t)g * 2048))[i4];
        int base = i4 * 4;
        int ci = base >> 7, cc = (base >> 4) & 7, jy = (base >> 2) & 3;
        float* dst = &wb[((ci * 4 + jy) * 4) * 8 + cc];
        dst[0] = w.x; dst[8] = w.y; dst[16] = w.z; dst[24] = w.w;
    }
    if (tid < 72) wb[2048 + tid] = cw3[g * 72 + tid];
    __syncthreads();

    // ---- convT2: [16,14,14] -> [8,28,28] ----
    if (v < 56 && b >= 0) {
        int my = v >> 2, co = (v & 3) * 2;
        u64 A2c[14];
#pragma unroll
        for (int m = 0; m < 14; m++) A2c[m] = 0ULL;
        if (px == 0) convt2_compute<0>(x2, wb, my, py, co, A2c);
        else         convt2_compute<1>(x2, wb, my, py, co, A2c);
        float bb0 = cb2[g * 8 + co], bb1 = cb2[g * 8 + co + 1];
        int oy = 2 * my + py;
#pragma unroll
        for (int m = 0; m < 14; m++) {
            int ox = 2 * m + px;
            float lo, hi; upk(A2c[m], lo, hi);
            x3[x3idx(co,     oy + 1, ox + 1)] = lrelu(lo + bb0);
            x3[x3idx(co + 1, oy + 1, ox + 1)] = lrelu(hi + bb1);
        }
    }
    __syncthreads();

    // ---- convT3 (stride1 k3 p1): [8,28,28] -> [1,28,28], tanh ----
    if (stid < 196 && b >= 0) {
        int oy = stid / 7, s = stid - oy * 7;        // s in 0..6
        float bb = cb3[g];
        float acc[4];
#pragma unroll
        for (int u = 0; u < 4; u++) acc[u] = bb;
        const float* w3 = wb + 2048;
        for (int ci = 0; ci < 8; ci++) {
#pragma unroll
            for (int jy = 0; jy < 3; jy++) {
                int row = oy + 2 - jy;
                int sw = row & 7;
                const float* base = x3 + (ci * 30 + row) * 32;
                float r[8];
                float4 v0 = *(const float4*)(base + ((s ^ sw) << 2));
                float4 v1 = *(const float4*)(base + (((s + 1) ^ sw) << 2));
                r[0] = v0.x; r[1] = v0.y; r[2] = v0.z; r[3] = v0.w;
                r[4] = v1.x; r[5] = v1.y; r[6] = v1.z; r[7] = v1.w;
                const float* wr = w3 + ci * 9 + jy * 3;
#pragma unroll
                for (int jx = 0; jx < 3; jx++) {
                    float wv = wr[jx];
#pragma unroll
                    for (int u = 0; u < 4; u++)
                        acc[u] += wv * r[u + 2 - jx];
                }
            }
        }
        float4 o;
        o.x = tanhf(acc[0]); o.y = tanhf(acc[1]);
        o.z = tanhf(acc[2]); o.w = tanhf(acc[3]);
        *(float4*)(out + (size_t)b * 784 + oy * 28 + s * 4) = o;
    }
}

// ---------------- launch ----------------
extern "C" void kernel_launch(void* const* d_in, const int* in_sizes, int n_in,
                              void* d_out, int out_size)
{
    (void)in_sizes; (void)n_in; (void)out_size;
    const float* z   = (const float*)d_in[0];
    const int*   gi  = (const int*)d_in[1];
    const float* W1  = (const float*)d_in[2];
    const float* b1  = (const float*)d_in[3];
    const float* W2  = (const float*)d_in[4];
    const float* b2  = (const float*)d_in[5];
    const float* cw1 = (const float*)d_in[6];
    const float* cb1 = (const float*)d_in[7];
    const float* cw2 = (const float*)d_in[8];
    const float* cb2 = (const float*)d_in[9];
    const float* cw3 = (const float*)d_in[10];
    const float* cb3 = (const float*)d_in[11];
    float* out = (float*)d_out;

    group_kernel<<<1, 256>>>(gi);
    fc1_kernel<<<NTILES, 256>>>(z, W1, b1);
    cudaFuncSetAttribute(fc2_kernel,
                         cudaFuncAttributeMaxDynamicSharedMemorySize,
                         FC2_SMEMF * 4);
    fc2_kernel<<<dim3(NTILES, 2), 224, FC2_SMEMF * 4>>>(W2, b2);
    cudaFuncSetAttribute(conv_kernel,
                         cudaFuncAttributeMaxDynamicSharedMemorySize,
                         SM_TOTALF * 4);
    conv_kernel<<<NTILES * 8, 512, SM_TOTALF * 4>>>(cw1, cb1, cw2, cb2,
                                                    cw3, cb3, out);
}